// round 2
// baseline (speedup 1.0000x reference)
#include <cuda_runtime.h>

#define Tt 2048
#define Bb 512
#define Cc 8
#define Hh 20

typedef unsigned long long u64;

__device__ __forceinline__ u64 pack2(float a, float b) {
    u64 r; asm("mov.b64 %0, {%1, %2};" : "=l"(r) : "f"(a), "f"(b)); return r;
}
__device__ __forceinline__ void unpack2(u64 v, float &a, float &b) {
    asm("mov.b64 {%0, %1}, %2;" : "=f"(a), "=f"(b) : "l"(v));
}
// packed dual-FMA: d.x += a.x*b.x ; d.y += a.y*b.y   (sm_100+ f32x2 pipe)
__device__ __forceinline__ void ffma2(u64 &d, u64 a, u64 b) {
    asm("fma.rn.f32x2 %0, %1, %2, %0;" : "+l"(d) : "l"(a), "l"(b));
}
__device__ __forceinline__ float hadd2(u64 v, float bias) {
    float a, b; unpack2(v, a, b); return a + b + bias;
}
__device__ __forceinline__ float sigm(float x) {
    float e = __expf(-x);
    return __fdividef(1.f, 1.f + e);
}
__device__ __forceinline__ float tanh_(float x) {
    float ax = fabsf(x);
    float e = __expf(-2.f * ax);          // e in (0,1], no overflow
    float t = __fdividef(1.f - e, 1.f + e);
    return copysignf(t, x);
}

// 2 warps per batch element: role 0 = layer-1 producer, role 1 = layer-2
// consumer one step behind, communicating h1 through a depth-2 smem ring
// with one named barrier per step. All weights live in registers.
__global__ void __launch_bounds__(256, 1) lstm2_kernel(
    const float* __restrict__ x,
    const float* __restrict__ Wih0, const float* __restrict__ Whh0,
    const float* __restrict__ bih0, const float* __restrict__ bhh0,
    const float* __restrict__ Wih1, const float* __restrict__ Whh1,
    const float* __restrict__ bih1, const float* __restrict__ bhh1,
    float* __restrict__ out)
{
    __shared__ __align__(16) float h1ring[4][2][24];  // per pair, 2 slots
    __shared__ __align__(16) float xbuf[4][2][8];     // x double buffer
    __shared__ __align__(16) float h2buf[4][24];      // warp-1 private h2

    const int tid   = threadIdx.x;
    const int w     = tid >> 5;
    const int lane  = tid & 31;
    const int pair  = w >> 1;
    // flip roles on pairs 2,3 so each SMSP gets one L1 + one L2 warp
    const int role  = (w & 1) ^ ((w >> 2) & 1);
    const int batch = blockIdx.x * 4 + pair;
    const int barid = pair + 1;

    for (int idx = tid; idx < 4 * 2 * 24; idx += 256) (&h1ring[0][0][0])[idx] = 0.f;
    for (int idx = tid; idx < 4 * 24;     idx += 256) (&h2buf[0][0])[idx]     = 0.f;
    if (role == 0 && lane < Cc)
        xbuf[pair][0][lane] = x[(size_t)batch * Cc + lane];   // x[t=0]
    __syncthreads();

    if (role == 0) {
        // ---------------- layer 1 ----------------
        u64 wx[4][4];    // 4 gates x 4 k-pairs over C=8 input dims
        u64 wh[4][10];   // 4 gates x 10 k-pairs over H=20 hidden dims
        float bias[4];
        if (lane < Hh) {
            #pragma unroll
            for (int g = 0; g < 4; g++) {
                const int row = g * Hh + lane;     // PyTorch gate order i,f,g,o
                const float* rx = Wih0 + row * Cc;
                #pragma unroll
                for (int kp = 0; kp < 4; kp++)  wx[g][kp] = pack2(rx[2*kp], rx[2*kp+1]);
                const float* rh = Whh0 + row * Hh;
                #pragma unroll
                for (int kp = 0; kp < 10; kp++) wh[g][kp] = pack2(rh[2*kp], rh[2*kp+1]);
                bias[g] = bih0[row] + bhh0[row];
            }
        }
        float c1 = 0.f;
        #pragma unroll 1
        for (int i = 0; i <= Tt; i++) {
            // prefetch x[i+1] (latency hidden by the step body)
            float xpre = 0.f;
            if (i + 1 < Tt && lane < Cc)
                xpre = __ldg(&x[(size_t)(i + 1) * Bb * Cc + batch * Cc + lane]);
            if (i < Tt) {
                u64 acc0 = 0, acc1 = 0, acc2 = 0, acc3 = 0;
                const u64* xp = (const u64*)&xbuf[pair][i & 1][0];
                const u64* hp = (const u64*)&h1ring[pair][(i + 1) & 1][0]; // h1[i-1]
                #pragma unroll
                for (int kp = 0; kp < 4; kp++) {
                    u64 v = xp[kp];
                    ffma2(acc0, wx[0][kp], v); ffma2(acc1, wx[1][kp], v);
                    ffma2(acc2, wx[2][kp], v); ffma2(acc3, wx[3][kp], v);
                }
                #pragma unroll
                for (int kp = 0; kp < 10; kp++) {
                    u64 v = hp[kp];
                    ffma2(acc0, wh[0][kp], v); ffma2(acc1, wh[1][kp], v);
                    ffma2(acc2, wh[2][kp], v); ffma2(acc3, wh[3][kp], v);
                }
                float ia = sigm (hadd2(acc0, bias[0]));
                float fa = sigm (hadd2(acc1, bias[1]));
                float ga = tanh_(hadd2(acc2, bias[2]));
                float oa = sigm (hadd2(acc3, bias[3]));
                c1 = fa * c1 + ia * ga;
                float h1 = oa * tanh_(c1);
                if (lane < Hh) h1ring[pair][i & 1][lane] = h1;
            }
            if (i + 1 < Tt && lane < Cc)
                xbuf[pair][(i + 1) & 1][lane] = xpre;
            asm volatile("bar.sync %0, 64;" :: "r"(barid) : "memory");
        }
    } else {
        // ---------------- layer 2 (one step behind) ----------------
        u64 w1[4][10];   // over h1
        u64 w2[4][10];   // over h2 (recurrent)
        float bias[4];
        if (lane < Hh) {
            #pragma unroll
            for (int g = 0; g < 4; g++) {
                const int row = g * Hh + lane;
                const float* r1 = Wih1 + row * Hh;
                const float* r2 = Whh1 + row * Hh;
                #pragma unroll
                for (int kp = 0; kp < 10; kp++) {
                    w1[g][kp] = pack2(r1[2*kp], r1[2*kp+1]);
                    w2[g][kp] = pack2(r2[2*kp], r2[2*kp+1]);
                }
                bias[g] = bih1[row] + bhh1[row];
            }
        }
        float c2 = 0.f;
        #pragma unroll 1
        for (int i = 0; i <= Tt; i++) {
            if (i >= 1) {
                const int t = i - 1;
                u64 acc0 = 0, acc1 = 0, acc2 = 0, acc3 = 0;
                const u64* h1p = (const u64*)&h1ring[pair][t & 1][0];
                const u64* h2p = (const u64*)&h2buf[pair][0];
                #pragma unroll
                for (int kp = 0; kp < 10; kp++) {
                    u64 v = h1p[kp];
                    ffma2(acc0, w1[0][kp], v); ffma2(acc1, w1[1][kp], v);
                    ffma2(acc2, w1[2][kp], v); ffma2(acc3, w1[3][kp], v);
                }
                #pragma unroll
                for (int kp = 0; kp < 10; kp++) {
                    u64 v = h2p[kp];
                    ffma2(acc0, w2[0][kp], v); ffma2(acc1, w2[1][kp], v);
                    ffma2(acc2, w2[2][kp], v); ffma2(acc3, w2[3][kp], v);
                }
                float ia = sigm (hadd2(acc0, bias[0]));
                float fa = sigm (hadd2(acc1, bias[1]));
                float ga = tanh_(hadd2(acc2, bias[2]));
                float oa = sigm (hadd2(acc3, bias[3]));
                c2 = fa * c2 + ia * ga;
                float h2 = oa * tanh_(c2);
                if (lane < Hh) {
                    out[(size_t)t * Bb * Hh + batch * Hh + lane] = h2;
                    h2buf[pair][lane] = h2;   // read happened above; bar orders next iter
                }
            }
            asm volatile("bar.sync %0, 64;" :: "r"(barid) : "memory");
        }
    }
}

extern "C" void kernel_launch(void* const* d_in, const int* in_sizes, int n_in,
                              void* d_out, int out_size) {
    lstm2_kernel<<<Bb / 4, 256>>>(
        (const float*)d_in[0],
        (const float*)d_in[1], (const float*)d_in[2],
        (const float*)d_in[3], (const float*)d_in[4],
        (const float*)d_in[5], (const float*)d_in[6],
        (const float*)d_in[7], (const float*)d_in[8],
        (float*)d_out);
}

// round 3
// speedup vs baseline: 3.0838x; 3.0838x over previous
#include <cuda_runtime.h>

#define Tt 2048
#define Bb 512
#define Cc 8
#define Hh 20
#define GRP 4
#define RING 8

typedef unsigned long long u64;

__device__ __forceinline__ u64 pack2(float a, float b) {
    u64 r; asm("mov.b64 %0, {%1, %2};" : "=l"(r) : "f"(a), "f"(b)); return r;
}
__device__ __forceinline__ void unpack2(u64 v, float &a, float &b) {
    asm("mov.b64 {%0, %1}, %2;" : "=f"(a), "=f"(b) : "l"(v));
}
// packed dual-FMA: d.x += a.x*b.x ; d.y += a.y*b.y
__device__ __forceinline__ void ffma2(u64 &d, u64 a, u64 b) {
    asm("fma.rn.f32x2 %0, %1, %2, %0;" : "+l"(d) : "l"(a), "l"(b));
}
__device__ __forceinline__ float hadd2(u64 v) {
    float a, b; unpack2(v, a, b); return a + b;
}
__device__ __forceinline__ float tanhfast(float x) {
    float y; asm("tanh.approx.f32 %0, %1;" : "=f"(y) : "f"(x)); return y;
}
__device__ __forceinline__ float sigmfast(float x) {
    return fmaf(tanhfast(0.5f * x), 0.5f, 0.5f);
}

// 2 warps per batch element: role 0 = layer-1 producer, role 1 = layer-2
// consumer one GROUP (4 steps) behind, through a depth-8 smem ring.
// One named barrier per 4 steps. All weights in registers; all smem reads
// software-pipelined off the critical path.
__global__ void __launch_bounds__(256, 1) lstm2_kernel(
    const float* __restrict__ x,
    const float* __restrict__ Wih0, const float* __restrict__ Whh0,
    const float* __restrict__ bih0, const float* __restrict__ bhh0,
    const float* __restrict__ Wih1, const float* __restrict__ Whh1,
    const float* __restrict__ bih1, const float* __restrict__ bhh1,
    float* __restrict__ out)
{
    __shared__ __align__(16) float h1ring[4][RING][24];
    __shared__ __align__(16) float h2buf[4][24];

    const int tid   = threadIdx.x;
    const int w     = tid >> 5;
    const int lane  = tid & 31;
    const int pair  = w >> 1;
    // flip roles on pairs 2,3 so each SMSP hosts one L1 + one L2 warp
    const int role  = (w & 1) ^ ((w >> 2) & 1);
    const int batch = blockIdx.x * 4 + pair;
    const int barid = pair + 1;

    if (role == 0) {
        // ---------------- layer 1 (producer) ----------------
        u64 wx[4][4], wh[4][10], binit[4];
        if (lane < Hh) {
            #pragma unroll
            for (int g = 0; g < 4; g++) {
                const int row = g * Hh + lane;          // gate order i,f,g,o
                const float* rx = Wih0 + row * Cc;
                #pragma unroll
                for (int kp = 0; kp < 4; kp++)  wx[g][kp] = pack2(rx[2*kp], rx[2*kp+1]);
                const float* rh = Whh0 + row * Hh;
                #pragma unroll
                for (int kp = 0; kp < 10; kp++) wh[g][kp] = pack2(rh[2*kp], rh[2*kp+1]);
                binit[g] = pack2(bih0[row] + bhh0[row], 0.f);
            }
        }
        // x prefetch pipeline, depth 2 (uniform LDG.128 pairs, broadcast)
        const ulonglong2* xb = ((const ulonglong2*)x) + (size_t)batch * 2;
        ulonglong2 x0a = xb[0],    x0b = xb[1];        // t = 0
        ulonglong2 x1a = xb[1024], x1b = xb[1025];     // t = 1
        u64 hp[10];
        #pragma unroll
        for (int kp = 0; kp < 10; kp++) hp[kp] = 0ull;
        float c1 = 0.f;

        #pragma unroll 1
        for (int p = 0; p < Tt / GRP; p++) {
            #pragma unroll
            for (int s = 0; s < GRP; s++) {
                const int t = p * GRP + s;
                u64 xv0 = x0a.x, xv1 = x0a.y, xv2 = x0b.x, xv3 = x0b.y;
                x0a = x1a; x0b = x1b;
                if (t + 2 < Tt) {                       // prefetch t+2
                    const ulonglong2* xq = xb + (size_t)(t + 2) * 1024;
                    x1a = xq[0]; x1b = xq[1];
                }
                u64 a0 = binit[0], a1 = binit[1], a2 = binit[2], a3 = binit[3];
                ffma2(a0, wx[0][0], xv0); ffma2(a1, wx[1][0], xv0);
                ffma2(a2, wx[2][0], xv0); ffma2(a3, wx[3][0], xv0);
                ffma2(a0, wx[0][1], xv1); ffma2(a1, wx[1][1], xv1);
                ffma2(a2, wx[2][1], xv1); ffma2(a3, wx[3][1], xv1);
                ffma2(a0, wx[0][2], xv2); ffma2(a1, wx[1][2], xv2);
                ffma2(a2, wx[2][2], xv2); ffma2(a3, wx[3][2], xv2);
                ffma2(a0, wx[0][3], xv3); ffma2(a1, wx[1][3], xv3);
                ffma2(a2, wx[2][3], xv3); ffma2(a3, wx[3][3], xv3);
                #pragma unroll
                for (int kp = 0; kp < 10; kp++) {
                    u64 v = hp[kp];
                    ffma2(a0, wh[0][kp], v); ffma2(a1, wh[1][kp], v);
                    ffma2(a2, wh[2][kp], v); ffma2(a3, wh[3][kp], v);
                }
                float ia = sigmfast(hadd2(a0));
                float fa = sigmfast(hadd2(a1));
                float ga = tanhfast(hadd2(a2));
                float oa = sigmfast(hadd2(a3));
                c1 = fmaf(fa, c1, ia * ga);
                float h1 = oa * tanhfast(c1);
                if (lane < Hh) h1ring[pair][t & (RING - 1)][lane] = h1;
                __syncwarp();
                // prefetch own broadcast pairs for next step (off critical path)
                const u64* rp = (const u64*)&h1ring[pair][t & (RING - 1)][0];
                #pragma unroll
                for (int kp = 0; kp < 10; kp++) hp[kp] = rp[kp];
            }
            asm volatile("bar.sync %0, 64;" :: "r"(barid) : "memory");
        }
    } else {
        // ---------------- layer 2 (consumer, one group behind) ----------------
        u64 w1[4][10], w2[4][10], binit[4];
        if (lane < Hh) {
            #pragma unroll
            for (int g = 0; g < 4; g++) {
                const int row = g * Hh + lane;
                const float* r1 = Wih1 + row * Hh;
                const float* r2 = Whh1 + row * Hh;
                #pragma unroll
                for (int kp = 0; kp < 10; kp++) {
                    w1[g][kp] = pack2(r1[2*kp], r1[2*kp+1]);
                    w2[g][kp] = pack2(r2[2*kp], r2[2*kp+1]);
                }
                binit[g] = pack2(bih1[row] + bhh1[row], 0.f);
            }
        }
        u64 h2p[10];
        #pragma unroll
        for (int kp = 0; kp < 10; kp++) h2p[kp] = 0ull;
        float c2 = 0.f;

        #pragma unroll 1
        for (int p = 0; p < Tt / GRP; p++) {
            asm volatile("bar.sync %0, 64;" :: "r"(barid) : "memory");
            u64 h1p[10];
            {
                const u64* rp = (const u64*)&h1ring[pair][(p * GRP) & (RING - 1)][0];
                #pragma unroll
                for (int kp = 0; kp < 10; kp++) h1p[kp] = rp[kp];
            }
            #pragma unroll
            for (int s = 0; s < GRP; s++) {
                const int t = p * GRP + s;
                u64 a0 = binit[0], a1 = binit[1], a2 = binit[2], a3 = binit[3];
                #pragma unroll
                for (int kp = 0; kp < 10; kp++) {
                    u64 v = h1p[kp];
                    ffma2(a0, w1[0][kp], v); ffma2(a1, w1[1][kp], v);
                    ffma2(a2, w1[2][kp], v); ffma2(a3, w1[3][kp], v);
                }
                // prefetch next step's h1 (already in ring, written pre-barrier)
                u64 h1n[10];
                if (s < GRP - 1) {
                    const u64* rp = (const u64*)&h1ring[pair][(t + 1) & (RING - 1)][0];
                    #pragma unroll
                    for (int kp = 0; kp < 10; kp++) h1n[kp] = rp[kp];
                }
                #pragma unroll
                for (int kp = 0; kp < 10; kp++) {
                    u64 v = h2p[kp];
                    ffma2(a0, w2[0][kp], v); ffma2(a1, w2[1][kp], v);
                    ffma2(a2, w2[2][kp], v); ffma2(a3, w2[3][kp], v);
                }
                float ia = sigmfast(hadd2(a0));
                float fa = sigmfast(hadd2(a1));
                float ga = tanhfast(hadd2(a2));
                float oa = sigmfast(hadd2(a3));
                c2 = fmaf(fa, c2, ia * ga);
                float h2 = oa * tanhfast(c2);
                if (lane < Hh) {
                    out[(size_t)t * Bb * Hh + batch * Hh + lane] = h2;
                    h2buf[pair][lane] = h2;
                }
                __syncwarp();
                const u64* rp2 = (const u64*)&h2buf[pair][0];
                #pragma unroll
                for (int kp = 0; kp < 10; kp++) h2p[kp] = rp2[kp];
                if (s < GRP - 1) {
                    #pragma unroll
                    for (int kp = 0; kp < 10; kp++) h1p[kp] = h1n[kp];
                }
            }
        }
    }
}

extern "C" void kernel_launch(void* const* d_in, const int* in_sizes, int n_in,
                              void* d_out, int out_size) {
    lstm2_kernel<<<Bb / 4, 256>>>(
        (const float*)d_in[0],
        (const float*)d_in[1], (const float*)d_in[2],
        (const float*)d_in[3], (const float*)d_in[4],
        (const float*)d_in[5], (const float*)d_in[6],
        (const float*)d_in[7], (const float*)d_in[8],
        (float*)d_out);
}